// round 1
// baseline (speedup 1.0000x reference)
#include <cuda_runtime.h>
#include <stdint.h>

// ---------------------------------------------------------------------------
// MoE-LoRA fused linear:  y = x @ W + (1/R) * (x @ A[l]) @ B[l] + bias
//   x: [T, D] f32, labels: [T] int32-or-int64, W: [D, D] f32,
//   A: [E, D, R] f32, B: [E, R, D] f32, bias: [D] f32, out: [T, D] f32
//   T = 16384, D = 1024, R = 8, E = 64
// ---------------------------------------------------------------------------

#define D_DIM 1024
#define R_DIM 8
#define SCALING (1.0f / 8.0f)
#define MAX_T 16384

// Scratch for per-token low-rank projection xa = x_t . A[label_t]  ([T, 8])
__device__ float g_xa[MAX_T * R_DIM];
// 1 if labels buffer is int64, 0 if int32 (decided on-device, deterministically)
__device__ int g_lab64;

// ---------------------------------------------------------------------------
// Kernel 0: classify label dtype. If the buffer is int64, every 8-byte word is
// a small non-negative expert id. If it is int32, 8-byte reads combine two
// labels -> values >= 2^32 whenever the odd-position label is nonzero, which
// is statistically certain over 256 probes of uniform labels in [0,64).
// ---------------------------------------------------------------------------
__global__ void detect_label_dtype_kernel(const void* labels, int T) {
    if (threadIdx.x != 0 || blockIdx.x != 0) return;
    const long long* p = (const long long*)labels;
    int n = T < 256 ? T : 256;   // always within even the int32 buffer (4*T bytes)
    int is64 = 1;
    for (int i = 0; i < n; ++i) {
        long long v = p[i];
        if (v < 0 || v >= (1LL << 31)) { is64 = 0; break; }
    }
    g_lab64 = is64;
}

__device__ __forceinline__ int load_label(const void* labels, int t) {
    if (g_lab64) return (int)((const long long*)labels)[t];
    return ((const int*)labels)[t];
}

// ---------------------------------------------------------------------------
// Kernel 1: xa[t][r] = sum_d x[t][d] * A[label_t][d][r]
// One warp per token. Lane strides D with step 32; A row (R=8 floats = 32 B)
// is read as two float4. Warp-shuffle tree reduce, lane 0 writes 8 floats.
// ---------------------------------------------------------------------------
__global__ void __launch_bounds__(256)
compute_xa_kernel(const float* __restrict__ x,
                  const void*  __restrict__ labels,
                  const float* __restrict__ A,
                  int T) {
    int t = blockIdx.x * 8 + (threadIdx.x >> 5);
    if (t >= T) return;
    int lane = threadIdx.x & 31;
    int e = load_label(labels, t);

    const float* xrow = x + (size_t)t * D_DIM;
    const float* Ae   = A + (size_t)e * D_DIM * R_DIM;

    float acc[R_DIM];
#pragma unroll
    for (int r = 0; r < R_DIM; ++r) acc[r] = 0.0f;

    for (int d = lane; d < D_DIM; d += 32) {
        float xv = xrow[d];
        const float4* ap = (const float4*)(Ae + (size_t)d * R_DIM);
        float4 a0 = ap[0];
        float4 a1 = ap[1];
        acc[0] += xv * a0.x;  acc[1] += xv * a0.y;
        acc[2] += xv * a0.z;  acc[3] += xv * a0.w;
        acc[4] += xv * a1.x;  acc[5] += xv * a1.y;
        acc[6] += xv * a1.z;  acc[7] += xv * a1.w;
    }

#pragma unroll
    for (int off = 16; off > 0; off >>= 1) {
#pragma unroll
        for (int r = 0; r < R_DIM; ++r)
            acc[r] += __shfl_down_sync(0xffffffffu, acc[r], off);
    }

    if (lane == 0) {
        float4* o = (float4*)(g_xa + (size_t)t * R_DIM);
        o[0] = make_float4(acc[0], acc[1], acc[2], acc[3]);
        o[1] = make_float4(acc[4], acc[5], acc[6], acc[7]);
    }
}

// ---------------------------------------------------------------------------
// Kernel 2: fused SGEMM + LoRA epilogue.
//   BM=BN=128, BK=8, 256 threads (16x16), 8x8 register tile per thread.
//   out[t][o] = sum_k x[t][k]*W[k][o] + SCALING * sum_r xa[t][r]*B[e_t][r][o]
//               + bias[o]
// ---------------------------------------------------------------------------
#define BM 128
#define BN 128
#define BK 8
#define TM 8
#define TN 8

__global__ void __launch_bounds__(256)
fused_gemm_lora_kernel(const float* __restrict__ x,
                       const void*  __restrict__ labels,
                       const float* __restrict__ W,
                       const float* __restrict__ B,
                       const float* __restrict__ bias,
                       float* __restrict__ out,
                       int T) {
    __shared__ float As[BK][BM];      // transposed x tile: As[k][row]
    __shared__ float Bs[BK][BN];      // W tile: Bs[k][col]
    __shared__ float s_xa[BM][R_DIM];
    __shared__ int   s_lab[BM];

    const int row0 = blockIdx.y * BM;
    const int col0 = blockIdx.x * BN;
    const int tid  = threadIdx.x;          // 0..255
    const int tx   = tid & 15;
    const int ty   = tid >> 4;

    // --- stage per-block token metadata (xa rows + labels) into smem ---
    {
        int t    = tid >> 1;                // 0..127
        int part = tid & 1;                 // which float4 of the 8-float row
        const float4* p = (const float4*)(g_xa + (size_t)(row0 + t) * R_DIM) + part;
        *(float4*)&s_xa[t][part * 4] = *p;
        if (tid < BM) s_lab[tid] = load_label(labels, row0 + tid);
    }

    float acc[TM][TN];
#pragma unroll
    for (int i = 0; i < TM; ++i)
#pragma unroll
        for (int j = 0; j < TN; ++j) acc[i][j] = 0.0f;

    // global load mapping
    const int a_row = tid >> 1;             // 0..127
    const int a_k4  = (tid & 1) * 4;        // 0 or 4
    const int b_k   = tid >> 5;             // 0..7
    const int b_c4  = (tid & 31) * 4;       // 0..124

    const float* xg = x + (size_t)(row0 + a_row) * D_DIM + a_k4;
    const float* wg = W + (size_t)b_k * D_DIM + col0 + b_c4;

    for (int k0 = 0; k0 < D_DIM; k0 += BK) {
        float4 av = *(const float4*)(xg + k0);
        float4 wv = *(const float4*)(wg + (size_t)k0 * D_DIM);

        __syncthreads();   // previous tile fully consumed (also fences s_xa)
        As[a_k4 + 0][a_row] = av.x;
        As[a_k4 + 1][a_row] = av.y;
        As[a_k4 + 2][a_row] = av.z;
        As[a_k4 + 3][a_row] = av.w;
        *(float4*)&Bs[b_k][b_c4] = wv;
        __syncthreads();

#pragma unroll
        for (int k = 0; k < BK; ++k) {
            float a[TM], b[TN];
            *(float4*)&a[0] = *(const float4*)&As[k][ty * TM];
            *(float4*)&a[4] = *(const float4*)&As[k][ty * TM + 4];
            *(float4*)&b[0] = *(const float4*)&Bs[k][tx * TN];
            *(float4*)&b[4] = *(const float4*)&Bs[k][tx * TN + 4];
#pragma unroll
            for (int i = 0; i < TM; ++i)
#pragma unroll
                for (int j = 0; j < TN; ++j)
                    acc[i][j] += a[i] * b[j];
        }
    }

    // --- epilogue: rank-8 LoRA correction + bias, vectorized stores ---
    const int r0 = ty * TM;     // local row base
    const int c0 = tx * TN;     // local col base

    float bvals[TN];
    *(float4*)&bvals[0] = *(const float4*)(bias + col0 + c0);
    *(float4*)&bvals[4] = *(const float4*)(bias + col0 + c0 + 4);

#pragma unroll
    for (int i = 0; i < TM; ++i) {
        const int lr = r0 + i;
        const int t  = row0 + lr;
        const int e  = s_lab[lr];

        float xa_r[R_DIM];
        *(float4*)&xa_r[0] = *(const float4*)&s_xa[lr][0];
        *(float4*)&xa_r[4] = *(const float4*)&s_xa[lr][4];

        const float* Be = B + ((size_t)e * R_DIM) * D_DIM + col0 + c0;
        float lora[TN];
#pragma unroll
        for (int j = 0; j < TN; ++j) lora[j] = 0.0f;
#pragma unroll
        for (int r = 0; r < R_DIM; ++r) {
            float xr = xa_r[r];
            float4 b0 = *(const float4*)(Be + (size_t)r * D_DIM);
            float4 b1 = *(const float4*)(Be + (size_t)r * D_DIM + 4);
            lora[0] += xr * b0.x;  lora[1] += xr * b0.y;
            lora[2] += xr * b0.z;  lora[3] += xr * b0.w;
            lora[4] += xr * b1.x;  lora[5] += xr * b1.y;
            lora[6] += xr * b1.z;  lora[7] += xr * b1.w;
        }

        float res[TN];
#pragma unroll
        for (int j = 0; j < TN; ++j)
            res[j] = acc[i][j] + SCALING * lora[j] + bvals[j];

        float* op = out + (size_t)t * D_DIM + col0 + c0;
        *(float4*)(op)     = *(const float4*)&res[0];
        *(float4*)(op + 4) = *(const float4*)&res[4];
    }
}

// ---------------------------------------------------------------------------
// kernel_launch — graph-capturable, allocation-free.
// Input order (metadata): x, labels, W, A, B, bias
// ---------------------------------------------------------------------------
extern "C" void kernel_launch(void* const* d_in, const int* in_sizes, int n_in,
                              void* d_out, int out_size) {
    const float* x      = (const float*)d_in[0];
    const void*  labels = (const void*) d_in[1];
    const float* W      = (const float*)d_in[2];
    const float* A      = (const float*)d_in[3];
    const float* B      = (const float*)d_in[4];
    const float* bias   = (const float*)d_in[5];
    float* out          = (float*)d_out;

    const int T = in_sizes[0] / D_DIM;

    detect_label_dtype_kernel<<<1, 32>>>(labels, T);

    compute_xa_kernel<<<(T + 7) / 8, 256>>>(x, labels, A, T);

    dim3 grid(D_DIM / BN, (T + BM - 1) / BM);
    fused_gemm_lora_kernel<<<grid, 256>>>(x, labels, W, B, bias, out, T);
}

// round 4
// speedup vs baseline: 1.6581x; 1.6581x over previous
#include <cuda_runtime.h>
#include <cuda_bf16.h>
#include <stdint.h>

// ===========================================================================
// MoE-LoRA fused linear:  y = x @ W + (1/R) * (x @ A[l]) @ B[l] + bias
//   x: [T,D] f32, labels: [T] i32/i64, W: [D,D] f32, A: [E,D,R] f32,
//   B: [E,R,D] f32, bias: [D] f32, out: [T,D] f32.  T=16384 D=1024 R=8 E=64
//
// bf16-split GEMM on tensor cores (mma.sync.m16n8k16):
//   x@W = x_hi@W_hi + x_hi@W_lo + x_lo@W_hi   (error ~1e-5)
// realized as a single K=3072 GEMM with per-chunk plane selection.
// cp.async 4-stage pipeline; LoRA rank-8 correction + bias fused in epilogue.
// ===========================================================================

#define D_DIM 1024
#define R_DIM 8
#define SCALING 0.125f
#define MAX_T 16384

#define BM 128
#define BN 128
#define BKB 32                       // bf16 K per stage
#define NSTAGE 4
#define NCHUNK 96                    // 3 terms * (1024/32)
#define ROWSTRIDE 40                 // bf16 elems per smem row (32 + 8 pad)
#define TILE_BYTES (128 * ROWSTRIDE * 2)      // 10240
#define STAGE_BYTES (2 * TILE_BYTES)          // 20480
#define SMEM_BYTES (NSTAGE * STAGE_BYTES)     // 81920 (epi reuses 67584)

// -------------------- device-global scratch (no allocs allowed) ------------
__device__ __align__(256) unsigned short g_x_hi[MAX_T * D_DIM];
__device__ __align__(256) unsigned short g_x_lo[MAX_T * D_DIM];
__device__ __align__(256) unsigned short g_w_hi[D_DIM * D_DIM];  // W^T hi
__device__ __align__(256) unsigned short g_w_lo[D_DIM * D_DIM];  // W^T lo
__device__ __align__(16)  float          g_xa[MAX_T * R_DIM];
__device__ int g_lab64;

// ------------------------------ helpers ------------------------------------
__device__ __forceinline__ uint32_t smem_u32(const void* p) {
    uint32_t a;
    asm("{ .reg .u64 t; cvta.to.shared.u64 t, %1; cvt.u32.u64 %0, t; }"
        : "=r"(a) : "l"(p));
    return a;
}
#define CP_ASYNC16(dst, src) \
    asm volatile("cp.async.cg.shared.global [%0], [%1], 16;" \
                 :: "r"(dst), "l"(src) : "memory")
#define CP_COMMIT() asm volatile("cp.async.commit_group;" ::: "memory")
#define CP_WAIT2()  asm volatile("cp.async.wait_group 2;" ::: "memory")
#define CP_WAIT0()  asm volatile("cp.async.wait_group 0;" ::: "memory")

#define LDSM4(r0, r1, r2, r3, addr) \
    asm volatile("ldmatrix.sync.aligned.m8n8.x4.shared.b16 {%0,%1,%2,%3}, [%4];" \
                 : "=r"(r0), "=r"(r1), "=r"(r2), "=r"(r3) : "r"(addr))

#define MMA16816(c, a, b) \
    asm volatile("mma.sync.aligned.m16n8k16.row.col.f32.bf16.bf16.f32 " \
                 "{%0,%1,%2,%3}, {%4,%5,%6,%7}, {%8,%9}, {%0,%1,%2,%3};" \
                 : "+f"((c)[0]), "+f"((c)[1]), "+f"((c)[2]), "+f"((c)[3]) \
                 : "r"((a)[0]), "r"((a)[1]), "r"((a)[2]), "r"((a)[3]), \
                   "r"((b)[0]), "r"((b)[1]))

// ---------------------------------------------------------------------------
// Kernel 0: classify labels dtype (int64 vs int32) deterministically.
// ---------------------------------------------------------------------------
__global__ void detect_label_dtype_kernel(const void* labels, int T) {
    if (threadIdx.x != 0 || blockIdx.x != 0) return;
    const long long* p = (const long long*)labels;
    int n = T < 256 ? T : 256;
    int is64 = 1;
    for (int i = 0; i < n; ++i) {
        long long v = p[i];
        if (v < 0 || v >= (1LL << 31)) { is64 = 0; break; }
    }
    g_lab64 = is64;
}
__device__ __forceinline__ int load_label(const void* labels, int t) {
    if (g_lab64) return (int)((const long long*)labels)[t];
    return ((const int*)labels)[t];
}

// ---------------------------------------------------------------------------
// Kernel 1: fused  x -> (x_hi, x_lo) bf16 split  +  xa = x . A[label]
// One warp per token; single pass over x.
// ---------------------------------------------------------------------------
__global__ void __launch_bounds__(256)
convert_x_xa_kernel(const float* __restrict__ x,
                    const void*  __restrict__ labels,
                    const float* __restrict__ A, int T) {
    int t = blockIdx.x * 8 + (threadIdx.x >> 5);
    if (t >= T) return;
    const int lane = threadIdx.x & 31;
    const int e = load_label(labels, t);
    const float* xrow = x + (size_t)t * D_DIM;
    const float* Ae   = A + (size_t)e * D_DIM * R_DIM;
    unsigned short* xh = g_x_hi + (size_t)t * D_DIM;
    unsigned short* xl = g_x_lo + (size_t)t * D_DIM;

    float acc[R_DIM];
#pragma unroll
    for (int r = 0; r < R_DIM; ++r) acc[r] = 0.0f;

#pragma unroll
    for (int i = 0; i < 8; ++i) {
        const int d = i * 128 + lane * 4;
        float4 v = *(const float4*)(xrow + d);

        ushort4 hi, lo;
        float vv[4] = {v.x, v.y, v.z, v.w};
        unsigned short hb[4], lb[4];
#pragma unroll
        for (int j = 0; j < 4; ++j) {
            __nv_bfloat16 h = __float2bfloat16_rn(vv[j]);
            __nv_bfloat16 l = __float2bfloat16_rn(vv[j] - __bfloat162float(h));
            hb[j] = *(unsigned short*)&h;
            lb[j] = *(unsigned short*)&l;
        }
        hi.x = hb[0]; hi.y = hb[1]; hi.z = hb[2]; hi.w = hb[3];
        lo.x = lb[0]; lo.y = lb[1]; lo.z = lb[2]; lo.w = lb[3];
        *(ushort4*)(xh + d) = hi;
        *(ushort4*)(xl + d) = lo;

#pragma unroll
        for (int j = 0; j < 4; ++j) {
            const float4* ap = (const float4*)(Ae + (size_t)(d + j) * R_DIM);
            float4 a0 = ap[0], a1 = ap[1];
            float xv = vv[j];
            acc[0] += xv * a0.x;  acc[1] += xv * a0.y;
            acc[2] += xv * a0.z;  acc[3] += xv * a0.w;
            acc[4] += xv * a1.x;  acc[5] += xv * a1.y;
            acc[6] += xv * a1.z;  acc[7] += xv * a1.w;
        }
    }
#pragma unroll
    for (int off = 16; off > 0; off >>= 1)
#pragma unroll
        for (int r = 0; r < R_DIM; ++r)
            acc[r] += __shfl_down_sync(0xffffffffu, acc[r], off);
    if (lane == 0) {
        float4* o = (float4*)(g_xa + (size_t)t * R_DIM);
        o[0] = make_float4(acc[0], acc[1], acc[2], acc[3]);
        o[1] = make_float4(acc[4], acc[5], acc[6], acc[7]);
    }
}

// ---------------------------------------------------------------------------
// Kernel 2: Wt[n][k] = W[k][n], split into bf16 hi/lo planes.
// ---------------------------------------------------------------------------
__global__ void __launch_bounds__(256)
convert_w_kernel(const float* __restrict__ W) {
    __shared__ float s[32][33];
    const int k0 = blockIdx.x * 32;
    const int n0 = blockIdx.y * 32;
    const int tx = threadIdx.x & 31;
    const int ty = threadIdx.x >> 5;
#pragma unroll
    for (int r = 0; r < 4; ++r) {
        int kk = ty + r * 8;
        s[kk][tx] = W[(size_t)(k0 + kk) * D_DIM + n0 + tx];
    }
    __syncthreads();
#pragma unroll
    for (int r = 0; r < 4; ++r) {
        int nn = ty + r * 8;
        float v = s[tx][nn];
        __nv_bfloat16 h = __float2bfloat16_rn(v);
        __nv_bfloat16 l = __float2bfloat16_rn(v - __bfloat162float(h));
        size_t o = (size_t)(n0 + nn) * D_DIM + k0 + tx;
        g_w_hi[o] = *(unsigned short*)&h;
        g_w_lo[o] = *(unsigned short*)&l;
    }
}

// ---------------------------------------------------------------------------
// Kernel 3: bf16x3 GEMM (mma.sync) + fused LoRA/bias epilogue.
//   256 threads = 8 warps (2M x 4N), warp tile 64x32, thread: 4x4 mma frags.
//   4-stage cp.async pipeline over 96 K-chunks of 32 bf16.
// ---------------------------------------------------------------------------
__global__ void __launch_bounds__(256, 1)
gemm_lora_kernel(const void*  __restrict__ labels,
                 const float* __restrict__ Bmat,
                 const float* __restrict__ bias,
                 float* __restrict__ out) {
    extern __shared__ char smem[];
    const uint32_t sbase = smem_u32(smem);
    const int tid  = threadIdx.x;
    const int row0 = blockIdx.y * BM;
    const int col0 = blockIdx.x * BN;

    const unsigned short* xplane[3] = {g_x_hi, g_x_hi, g_x_lo};
    const unsigned short* wplane[3] = {g_w_hi, g_w_lo, g_w_hi};

    // cp.async geometry: 2 rows of A + 2 rows of B per thread, 16B each
    const int lrow = tid >> 2;           // 0..63
    const int lseg = tid & 3;            // 16B segment within 64B row

    // warp/lane geometry
    const int warp = tid >> 5, lane = tid & 31;
    const int wm = warp >> 2, wn = warp & 3;
    const uint32_t a_lm_off =
        (uint32_t)((wm * 64 + (lane & 15)) * ROWSTRIDE + (lane >> 4) * 8) * 2;
    const uint32_t b_lm_n = (uint32_t)((lane >> 4) * 8 + (lane & 7));
    const uint32_t b_lm_k = (uint32_t)(((lane >> 3) & 1) * 8);

    float c[4][4][4];
#pragma unroll
    for (int i = 0; i < 4; ++i)
#pragma unroll
        for (int j = 0; j < 4; ++j)
#pragma unroll
            for (int q = 0; q < 4; ++q) c[i][j][q] = 0.0f;

    auto issue = [&](int cn) {
        const int term = cn >> 5;
        const int kk   = (cn & 31) * BKB;
        const unsigned short* xs = xplane[term];
        const unsigned short* ws = wplane[term];
        const uint32_t sa = sbase + (uint32_t)(cn & 3) * STAGE_BYTES;
#pragma unroll
        for (int h = 0; h < 2; ++h) {
            const int r = lrow + h * 64;
            const void* src = xs + (size_t)(row0 + r) * D_DIM + kk + lseg * 8;
            CP_ASYNC16(sa + (uint32_t)(r * (ROWSTRIDE * 2) + lseg * 16), src);
        }
#pragma unroll
        for (int h = 0; h < 2; ++h) {
            const int r = lrow + h * 64;
            const void* src = ws + (size_t)(col0 + r) * D_DIM + kk + lseg * 8;
            CP_ASYNC16(sa + (uint32_t)(TILE_BYTES + r * (ROWSTRIDE * 2) + lseg * 16), src);
        }
    };

    // prologue: fill 3 stages
#pragma unroll
    for (int cn = 0; cn < NSTAGE - 1; ++cn) { issue(cn); CP_COMMIT(); }

    for (int ch = 0; ch < NCHUNK; ++ch) {
        CP_WAIT2();
        __syncthreads();
        const uint32_t sa = sbase + (uint32_t)(ch & 3) * STAGE_BYTES;

#pragma unroll
        for (int ks = 0; ks < 2; ++ks) {
            uint32_t a[4][4], b[4][2];
#pragma unroll
            for (int mf = 0; mf < 4; ++mf) {
                uint32_t addr = sa + a_lm_off +
                                (uint32_t)(mf * 16 * ROWSTRIDE + ks * 16) * 2;
                LDSM4(a[mf][0], a[mf][1], a[mf][2], a[mf][3], addr);
            }
#pragma unroll
            for (int p = 0; p < 2; ++p) {
                // FIX (round 4): include the warp's N offset (wn*32) — it was
                // missing, so every warp consumed W columns 0..31.
                uint32_t addr = sa + TILE_BYTES +
                    (uint32_t)((wn * 32 + p * 16 + b_lm_n) * ROWSTRIDE +
                               ks * 16 + b_lm_k) * 2;
                uint32_t r0, r1, r2, r3;
                LDSM4(r0, r1, r2, r3, addr);
                b[2 * p][0] = r0;  b[2 * p][1] = r1;
                b[2 * p + 1][0] = r2;  b[2 * p + 1][1] = r3;
            }
#pragma unroll
            for (int mf = 0; mf < 4; ++mf)
#pragma unroll
                for (int nf = 0; nf < 4; ++nf)
                    MMA16816(c[mf][nf], a[mf], b[nf]);
        }

        if (ch + NSTAGE - 1 < NCHUNK) issue(ch + NSTAGE - 1);
        CP_COMMIT();
    }
    CP_WAIT0();
    __syncthreads();

    // ---- stage accumulators to smem (reuse pipeline smem) ----
    float* acc_s = (float*)smem;                 // [128][132]
    const int g = lane >> 2, q = lane & 3;
#pragma unroll
    for (int mf = 0; mf < 4; ++mf) {
        const int r1 = wm * 64 + mf * 16 + g;
#pragma unroll
        for (int nf = 0; nf < 4; ++nf) {
            const int cc = wn * 32 + nf * 8 + q * 2;
            *(float2*)&acc_s[r1 * 132 + cc]       = make_float2(c[mf][nf][0], c[mf][nf][1]);
            *(float2*)&acc_s[(r1 + 8) * 132 + cc] = make_float2(c[mf][nf][2], c[mf][nf][3]);
        }
    }
    __syncthreads();

    // ---- epilogue: per-token rank-8 LoRA + bias, vectorized ----
    const int lr  = tid >> 1;            // 0..127
    const int chf = (tid & 1) * 64;      // column half
    const int t   = row0 + lr;
    const int e   = load_label(labels, t);

    float xs[R_DIM];
    {
        const float4* p = (const float4*)(g_xa + (size_t)t * R_DIM);
        float4 a0 = p[0], a1 = p[1];
        xs[0] = SCALING * a0.x; xs[1] = SCALING * a0.y;
        xs[2] = SCALING * a0.z; xs[3] = SCALING * a0.w;
        xs[4] = SCALING * a1.x; xs[5] = SCALING * a1.y;
        xs[6] = SCALING * a1.z; xs[7] = SCALING * a1.w;
    }

    float res[64];
#pragma unroll
    for (int v = 0; v < 16; ++v)
        *(float4*)&res[v * 4] = *(const float4*)&acc_s[lr * 132 + chf + v * 4];

    const float* Be = Bmat + (size_t)e * R_DIM * D_DIM + col0 + chf;
#pragma unroll
    for (int r = 0; r < R_DIM; ++r) {
        const float4* bp = (const float4*)(Be + (size_t)r * D_DIM);
        const float xr = xs[r];
#pragma unroll
        for (int v = 0; v < 16; ++v) {
            float4 b4 = bp[v];
            res[v * 4 + 0] += xr * b4.x;
            res[v * 4 + 1] += xr * b4.y;
            res[v * 4 + 2] += xr * b4.z;
            res[v * 4 + 3] += xr * b4.w;
        }
    }
    const float4* bi = (const float4*)(bias + col0 + chf);
    float* op = out + (size_t)t * D_DIM + col0 + chf;
#pragma unroll
    for (int v = 0; v < 16; ++v) {
        float4 bv = bi[v];
        float4 o4 = make_float4(res[v * 4 + 0] + bv.x, res[v * 4 + 1] + bv.y,
                                res[v * 4 + 2] + bv.z, res[v * 4 + 3] + bv.w);
        ((float4*)op)[v] = o4;
    }
}

// ---------------------------------------------------------------------------
// kernel_launch — graph-capturable, allocation-free.
// Inputs: x, labels, W, A, B, bias
// ---------------------------------------------------------------------------
extern "C" void kernel_launch(void* const* d_in, const int* in_sizes, int n_in,
                              void* d_out, int out_size) {
    const float* x      = (const float*)d_in[0];
    const void*  labels = (const void*) d_in[1];
    const float* W      = (const float*)d_in[2];
    const float* A      = (const float*)d_in[3];
    const float* B      = (const float*)d_in[4];
    const float* bias   = (const float*)d_in[5];
    float* out          = (float*)d_out;

    const int T = in_sizes[0] / D_DIM;

    detect_label_dtype_kernel<<<1, 32>>>(labels, T);
    convert_x_xa_kernel<<<(T + 7) / 8, 256>>>(x, labels, A, T);
    convert_w_kernel<<<dim3(D_DIM / 32, D_DIM / 32), 256>>>(W);

    static int smem_set = 0;
    if (!smem_set) {
        cudaFuncSetAttribute(gemm_lora_kernel,
                             cudaFuncAttributeMaxDynamicSharedMemorySize, SMEM_BYTES);
        smem_set = 1;
    }
    dim3 grid(D_DIM / BN, T / BM);
    gemm_lora_kernel<<<grid, 256, SMEM_BYTES>>>(labels, B, bias, out);
}

// round 5
// speedup vs baseline: 1.8873x; 1.1382x over previous
#include <cuda_runtime.h>
#include <cuda_bf16.h>
#include <stdint.h>

// ===========================================================================
// MoE-LoRA fused linear:  y = x @ W + (1/R) * (x @ A[l]) @ B[l] + bias
//   x: [T,D] f32, labels: [T] i32/i64, W: [D,D] f32, A: [E,D,R] f32,
//   B: [E,R,D] f32, bias: [D] f32, out: [T,D] f32.  T=16384 D=1024 R=8 E=64
//
// bf16-split GEMM on tensor cores (mma.sync.m16n8k16):
//   x@W = x_hi@W_hi + x_hi@W_lo + x_lo@W_hi
// Round 5: plane-shared K-chunks — each chunk loads x_hi/x_lo/W_hi/W_lo once
// and issues all 3 term-products, cutting L1 traffic 33% and barriers 3x.
// ===========================================================================

#define D_DIM 1024
#define R_DIM 8
#define SCALING 0.125f
#define MAX_T 16384

#define BM 128
#define BN 128
#define BKB 32                       // bf16 K per chunk (per plane)
#define NSTAGE 4
#define NCHUNK 32                    // 1024 / 32
#define ROWSTRIDE 40                 // bf16 elems per smem row (32 + 8 pad)
#define PLANE_BYTES (128 * ROWSTRIDE * 2)     // 10240
#define STAGE_BYTES (4 * PLANE_BYTES)         // 40960: xh | xl | wh | wl
#define SMEM_BYTES (NSTAGE * STAGE_BYTES)     // 163840

// -------------------- device-global scratch (no allocs allowed) ------------
__device__ __align__(256) unsigned short g_x_hi[MAX_T * D_DIM];
__device__ __align__(256) unsigned short g_x_lo[MAX_T * D_DIM];
__device__ __align__(256) unsigned short g_w_hi[D_DIM * D_DIM];  // W^T hi
__device__ __align__(256) unsigned short g_w_lo[D_DIM * D_DIM];  // W^T lo
__device__ __align__(16)  float          g_xa[MAX_T * R_DIM];
__device__ int g_lab64;

// ------------------------------ helpers ------------------------------------
__device__ __forceinline__ uint32_t smem_u32(const void* p) {
    uint32_t a;
    asm("{ .reg .u64 t; cvta.to.shared.u64 t, %1; cvt.u32.u64 %0, t; }"
        : "=r"(a) : "l"(p));
    return a;
}
#define CP_ASYNC16(dst, src) \
    asm volatile("cp.async.cg.shared.global [%0], [%1], 16;" \
                 :: "r"(dst), "l"(src) : "memory")
#define CP_COMMIT() asm volatile("cp.async.commit_group;" ::: "memory")
#define CP_WAIT2()  asm volatile("cp.async.wait_group 2;" ::: "memory")
#define CP_WAIT0()  asm volatile("cp.async.wait_group 0;" ::: "memory")

#define LDSM4(r0, r1, r2, r3, addr) \
    asm volatile("ldmatrix.sync.aligned.m8n8.x4.shared.b16 {%0,%1,%2,%3}, [%4];" \
                 : "=r"(r0), "=r"(r1), "=r"(r2), "=r"(r3) : "r"(addr))

#define MMA16816(c, a, b) \
    asm volatile("mma.sync.aligned.m16n8k16.row.col.f32.bf16.bf16.f32 " \
                 "{%0,%1,%2,%3}, {%4,%5,%6,%7}, {%8,%9}, {%0,%1,%2,%3};" \
                 : "+f"((c)[0]), "+f"((c)[1]), "+f"((c)[2]), "+f"((c)[3]) \
                 : "r"((a)[0]), "r"((a)[1]), "r"((a)[2]), "r"((a)[3]), \
                   "r"((b)[0]), "r"((b)[1]))

// ---------------------------------------------------------------------------
// Kernel 0: classify labels dtype (int64 vs int32) deterministically.
// ---------------------------------------------------------------------------
__global__ void detect_label_dtype_kernel(const void* labels, int T) {
    if (threadIdx.x != 0 || blockIdx.x != 0) return;
    const long long* p = (const long long*)labels;
    int n = T < 256 ? T : 256;
    int is64 = 1;
    for (int i = 0; i < n; ++i) {
        long long v = p[i];
        if (v < 0 || v >= (1LL << 31)) { is64 = 0; break; }
    }
    g_lab64 = is64;
}
__device__ __forceinline__ int load_label(const void* labels, int t) {
    if (g_lab64) return (int)((const long long*)labels)[t];
    return ((const int*)labels)[t];
}

// ---------------------------------------------------------------------------
// Kernel 1: fused  x -> (x_hi, x_lo) bf16 split  +  xa = x . A[label]
// ---------------------------------------------------------------------------
__global__ void __launch_bounds__(256)
convert_x_xa_kernel(const float* __restrict__ x,
                    const void*  __restrict__ labels,
                    const float* __restrict__ A, int T) {
    int t = blockIdx.x * 8 + (threadIdx.x >> 5);
    if (t >= T) return;
    const int lane = threadIdx.x & 31;
    const int e = load_label(labels, t);
    const float* xrow = x + (size_t)t * D_DIM;
    const float* Ae   = A + (size_t)e * D_DIM * R_DIM;
    unsigned short* xh = g_x_hi + (size_t)t * D_DIM;
    unsigned short* xl = g_x_lo + (size_t)t * D_DIM;

    float acc[R_DIM];
#pragma unroll
    for (int r = 0; r < R_DIM; ++r) acc[r] = 0.0f;

#pragma unroll
    for (int i = 0; i < 8; ++i) {
        const int d = i * 128 + lane * 4;
        float4 v = *(const float4*)(xrow + d);

        ushort4 hi, lo;
        float vv[4] = {v.x, v.y, v.z, v.w};
        unsigned short hb[4], lb[4];
#pragma unroll
        for (int j = 0; j < 4; ++j) {
            __nv_bfloat16 h = __float2bfloat16_rn(vv[j]);
            __nv_bfloat16 l = __float2bfloat16_rn(vv[j] - __bfloat162float(h));
            hb[j] = *(unsigned short*)&h;
            lb[j] = *(unsigned short*)&l;
        }
        hi.x = hb[0]; hi.y = hb[1]; hi.z = hb[2]; hi.w = hb[3];
        lo.x = lb[0]; lo.y = lb[1]; lo.z = lb[2]; lo.w = lb[3];
        *(ushort4*)(xh + d) = hi;
        *(ushort4*)(xl + d) = lo;

#pragma unroll
        for (int j = 0; j < 4; ++j) {
            const float4* ap = (const float4*)(Ae + (size_t)(d + j) * R_DIM);
            float4 a0 = ap[0], a1 = ap[1];
            float xv = vv[j];
            acc[0] += xv * a0.x;  acc[1] += xv * a0.y;
            acc[2] += xv * a0.z;  acc[3] += xv * a0.w;
            acc[4] += xv * a1.x;  acc[5] += xv * a1.y;
            acc[6] += xv * a1.z;  acc[7] += xv * a1.w;
        }
    }
#pragma unroll
    for (int off = 16; off > 0; off >>= 1)
#pragma unroll
        for (int r = 0; r < R_DIM; ++r)
            acc[r] += __shfl_down_sync(0xffffffffu, acc[r], off);
    if (lane == 0) {
        float4* o = (float4*)(g_xa + (size_t)t * R_DIM);
        o[0] = make_float4(acc[0], acc[1], acc[2], acc[3]);
        o[1] = make_float4(acc[4], acc[5], acc[6], acc[7]);
    }
}

// ---------------------------------------------------------------------------
// Kernel 2: Wt[n][k] = W[k][n], split into bf16 hi/lo planes.
// ---------------------------------------------------------------------------
__global__ void __launch_bounds__(256)
convert_w_kernel(const float* __restrict__ W) {
    __shared__ float s[32][33];
    const int k0 = blockIdx.x * 32;
    const int n0 = blockIdx.y * 32;
    const int tx = threadIdx.x & 31;
    const int ty = threadIdx.x >> 5;
#pragma unroll
    for (int r = 0; r < 4; ++r) {
        int kk = ty + r * 8;
        s[kk][tx] = W[(size_t)(k0 + kk) * D_DIM + n0 + tx];
    }
    __syncthreads();
#pragma unroll
    for (int r = 0; r < 4; ++r) {
        int nn = ty + r * 8;
        float v = s[tx][nn];
        __nv_bfloat16 h = __float2bfloat16_rn(v);
        __nv_bfloat16 l = __float2bfloat16_rn(v - __bfloat162float(h));
        size_t o = (size_t)(n0 + nn) * D_DIM + k0 + tx;
        g_w_hi[o] = *(unsigned short*)&h;
        g_w_lo[o] = *(unsigned short*)&l;
    }
}

// ---------------------------------------------------------------------------
// Kernel 3: plane-shared bf16x3 GEMM + fused LoRA/bias epilogue.
//   256 threads = 8 warps (2M x 4N), warp tile 64x32.
//   Chunk = 32 K: planes xh|xl|wh|wl staged once, 3 term-products issued.
// ---------------------------------------------------------------------------
__global__ void __launch_bounds__(256, 1)
gemm_lora_kernel(const void*  __restrict__ labels,
                 const float* __restrict__ Bmat,
                 const float* __restrict__ bias,
                 float* __restrict__ out) {
    extern __shared__ char smem[];
    const uint32_t sbase = smem_u32(smem);
    const int tid  = threadIdx.x;
    const int row0 = blockIdx.y * BM;
    const int col0 = blockIdx.x * BN;

    // cp.async geometry: per plane, 2 rows per thread, 16B each
    const int lrow = tid >> 2;           // 0..63
    const int lseg = tid & 3;            // 16B segment within 64B row

    // warp/lane geometry
    const int warp = tid >> 5, lane = tid & 31;
    const int wm = warp >> 2, wn = warp & 3;
    const uint32_t a_lm_off =
        (uint32_t)((wm * 64 + (lane & 15)) * ROWSTRIDE + (lane >> 4) * 8) * 2;
    const uint32_t b_lm_off =
        (uint32_t)((wn * 32 + (lane >> 4) * 8 + (lane & 7)) * ROWSTRIDE +
                   ((lane >> 3) & 1) * 8) * 2;

    float c[4][4][4];
#pragma unroll
    for (int i = 0; i < 4; ++i)
#pragma unroll
        for (int j = 0; j < 4; ++j)
#pragma unroll
            for (int q = 0; q < 4; ++q) c[i][j][q] = 0.0f;

    auto issue = [&](int cn) {
        const int kk = cn * BKB;
        const uint32_t sa = sbase + (uint32_t)(cn & (NSTAGE - 1)) * STAGE_BYTES;
        const unsigned short* planes[4];
        planes[0] = g_x_hi + (size_t)row0 * D_DIM;
        planes[1] = g_x_lo + (size_t)row0 * D_DIM;
        planes[2] = g_w_hi + (size_t)col0 * D_DIM;
        planes[3] = g_w_lo + (size_t)col0 * D_DIM;
#pragma unroll
        for (int pl = 0; pl < 4; ++pl) {
#pragma unroll
            for (int h = 0; h < 2; ++h) {
                const int r = lrow + h * 64;
                const void* src = planes[pl] + (size_t)r * D_DIM + kk + lseg * 8;
                CP_ASYNC16(sa + (uint32_t)(pl * PLANE_BYTES +
                                           r * (ROWSTRIDE * 2) + lseg * 16), src);
            }
        }
    };

    // prologue: fill 3 stages
#pragma unroll
    for (int cn = 0; cn < NSTAGE - 1; ++cn) { issue(cn); CP_COMMIT(); }

    for (int ch = 0; ch < NCHUNK; ++ch) {
        CP_WAIT2();
        __syncthreads();
        const uint32_t sa = sbase + (uint32_t)(ch & (NSTAGE - 1)) * STAGE_BYTES;

#pragma unroll
        for (int ks = 0; ks < 2; ++ks) {
            uint32_t ah[4][4], al[4][4], bh[4][2], bl[4][2];
#pragma unroll
            for (int mf = 0; mf < 4; ++mf) {
                uint32_t ao = a_lm_off + (uint32_t)(mf * 16 * ROWSTRIDE + ks * 16) * 2;
                LDSM4(ah[mf][0], ah[mf][1], ah[mf][2], ah[mf][3], sa + ao);
                LDSM4(al[mf][0], al[mf][1], al[mf][2], al[mf][3],
                      sa + PLANE_BYTES + ao);
            }
#pragma unroll
            for (int p = 0; p < 2; ++p) {
                uint32_t bo = b_lm_off + (uint32_t)(p * 16 * ROWSTRIDE + ks * 16) * 2;
                uint32_t r0, r1, r2, r3;
                LDSM4(r0, r1, r2, r3, sa + 2 * PLANE_BYTES + bo);
                bh[2 * p][0] = r0;      bh[2 * p][1] = r1;
                bh[2 * p + 1][0] = r2;  bh[2 * p + 1][1] = r3;
                LDSM4(r0, r1, r2, r3, sa + 3 * PLANE_BYTES + bo);
                bl[2 * p][0] = r0;      bl[2 * p][1] = r1;
                bl[2 * p + 1][0] = r2;  bl[2 * p + 1][1] = r3;
            }
            // 3 term-products from resident fragments: hi*Hi, hi*Lo, lo*Hi
#pragma unroll
            for (int mf = 0; mf < 4; ++mf)
#pragma unroll
                for (int nf = 0; nf < 4; ++nf) {
                    MMA16816(c[mf][nf], ah[mf], bh[nf]);
                    MMA16816(c[mf][nf], ah[mf], bl[nf]);
                    MMA16816(c[mf][nf], al[mf], bh[nf]);
                }
        }

        if (ch + NSTAGE - 1 < NCHUNK) { issue(ch + NSTAGE - 1); }
        CP_COMMIT();
    }
    CP_WAIT0();
    __syncthreads();

    // ---- stage accumulators to smem (reuse pipeline smem) ----
    float* acc_s = (float*)smem;                 // [128][132]
    const int g = lane >> 2, q = lane & 3;
#pragma unroll
    for (int mf = 0; mf < 4; ++mf) {
        const int r1 = wm * 64 + mf * 16 + g;
#pragma unroll
        for (int nf = 0; nf < 4; ++nf) {
            const int cc = wn * 32 + nf * 8 + q * 2;
            *(float2*)&acc_s[r1 * 132 + cc]       = make_float2(c[mf][nf][0], c[mf][nf][1]);
            *(float2*)&acc_s[(r1 + 8) * 132 + cc] = make_float2(c[mf][nf][2], c[mf][nf][3]);
        }
    }
    __syncthreads();

    // ---- epilogue: per-token rank-8 LoRA + bias, vectorized ----
    const int lr  = tid >> 1;            // 0..127
    const int chf = (tid & 1) * 64;      // column half
    const int t   = row0 + lr;
    const int e   = load_label(labels, t);

    float xs[R_DIM];
    {
        const float4* p = (const float4*)(g_xa + (size_t)t * R_DIM);
        float4 a0 = p[0], a1 = p[1];
        xs[0] = SCALING * a0.x; xs[1] = SCALING * a0.y;
        xs[2] = SCALING * a0.z; xs[3] = SCALING * a0.w;
        xs[4] = SCALING * a1.x; xs[5] = SCALING * a1.y;
        xs[6] = SCALING * a1.z; xs[7] = SCALING * a1.w;
    }

    float res[64];
#pragma unroll
    for (int v = 0; v < 16; ++v)
        *(float4*)&res[v * 4] = *(const float4*)&acc_s[lr * 132 + chf + v * 4];

    const float* Be = Bmat + (size_t)e * R_DIM * D_DIM + col0 + chf;
#pragma unroll
    for (int r = 0; r < R_DIM; ++r) {
        const float4* bp = (const float4*)(Be + (size_t)r * D_DIM);
        const float xr = xs[r];
#pragma unroll
        for (int v = 0; v < 16; ++v) {
            float4 b4 = bp[v];
            res[v * 4 + 0] += xr * b4.x;
            res[v * 4 + 1] += xr * b4.y;
            res[v * 4 + 2] += xr * b4.z;
            res[v * 4 + 3] += xr * b4.w;
        }
    }
    const float4* bi = (const float4*)(bias + col0 + chf);
    float* op = out + (size_t)t * D_DIM + col0 + chf;
#pragma unroll
    for (int v = 0; v < 16; ++v) {
        float4 bv = bi[v];
        float4 o4 = make_float4(res[v * 4 + 0] + bv.x, res[v * 4 + 1] + bv.y,
                                res[v * 4 + 2] + bv.z, res[v * 4 + 3] + bv.w);
        ((float4*)op)[v] = o4;
    }
}

// ---------------------------------------------------------------------------
// kernel_launch — graph-capturable, allocation-free.
// Inputs: x, labels, W, A, B, bias
// ---------------------------------------------------------------------------
extern "C" void kernel_launch(void* const* d_in, const int* in_sizes, int n_in,
                              void* d_out, int out_size) {
    const float* x      = (const float*)d_in[0];
    const void*  labels = (const void*) d_in[1];
    const float* W      = (const float*)d_in[2];
    const float* A      = (const float*)d_in[3];
    const float* B      = (const float*)d_in[4];
    const float* bias   = (const float*)d_in[5];
    float* out          = (float*)d_out;

    const int T = in_sizes[0] / D_DIM;

    detect_label_dtype_kernel<<<1, 32>>>(labels, T);
    convert_x_xa_kernel<<<(T + 7) / 8, 256>>>(x, labels, A, T);
    convert_w_kernel<<<dim3(D_DIM / 32, D_DIM / 32), 256>>>(W);

    static int smem_set = 0;
    if (!smem_set) {
        cudaFuncSetAttribute(gemm_lora_kernel,
                             cudaFuncAttributeMaxDynamicSharedMemorySize, SMEM_BYTES);
        smem_set = 1;
    }
    dim3 grid(D_DIM / BN, T / BM);
    gemm_lora_kernel<<<grid, 256, SMEM_BYTES>>>(labels, B, bias, out);
}